// round 10
// baseline (speedup 1.0000x reference)
#include <cuda_runtime.h>
#include <cuda_bf16.h>
#include <math.h>
#include <stdlib.h>
#include <stdint.h>

// ---------------------------------------------------------------------------
// BrainGCN: 2x GCNConv(+tanh) then 2 FC layers.
// R9: fast tanh (expf-based, ~2ulp abs err) replacing libm tanhf;
// gemm1 split into 2 column-halves (smem 135->69.6KB, 3 CTA/SM);
// dtype detect folded into convert_count. Rest as R8.
// ---------------------------------------------------------------------------

namespace {
struct EnvInit {  // must run before any CUDA call (lazy-load workaround, R4)
    EnvInit() { setenv("CUDA_MODULE_LOADING", "EAGER", 1); }
};
EnvInit g_env_init;
}

#define MAX_NODES 50000
#define MAX_EDGES 800000

__device__ int   g_deg[MAX_NODES];
__device__ float g_dinv[MAX_NODES];
__device__ int   g_src[MAX_EDGES];
__device__ int   g_dst[MAX_EDGES];
__device__ int   g_rowptr[MAX_NODES + 1];
__device__ int   g_cursor[MAX_NODES];
__device__ int2  g_csr[MAX_EDGES];       // {src, __float_as_int(coef)}

// Aliasing: big1 = xw1[M,128], later xw2[M,64] + agg2[M,64]. big2 = h1[M,128].
__device__ float g_big1[MAX_NODES * 128];
__device__ float g_big2[MAX_NODES * 128];

// ---------------------------------------------------------------------------
// Fast tanh: (e^2x - 1)/(e^2x + 1). __expf = MUFU.EX2 path, __fdividef fast.
// Absolute error ~2 ulp of 1.0 (~2.4e-7); clamp avoids inf/inf.
// ---------------------------------------------------------------------------
__device__ __forceinline__ float fast_tanhf(float x) {
    float xc = fminf(fmaxf(x, -15.0f), 15.0f);
    float t = __expf(2.0f * xc);
    return __fdividef(t - 1.0f, t + 1.0f);
}

// ---------------------------------------------------------------------------
// Fused convert + degree count. Each block derives is64 locally from the
// first 16 entries (two L2-broadcast lines) -- no separate kernel/flag dep.
// ---------------------------------------------------------------------------
__global__ void convert_count_kernel(const void* __restrict__ ei, int E) {
    const unsigned int* w = (const unsigned int*)ei;
    int is64 = 1;
    #pragma unroll
    for (int i = 0; i < 16; i++)
        if (w[2 * i + 1] != 0u) is64 = 0;

    int e = blockIdx.x * blockDim.x + threadIdx.x;
    if (e >= E) return;
    int s, d;
    if (is64) {
        s = (int)((const long long*)ei)[e];
        d = (int)((const long long*)ei)[E + e];
    } else {
        s = ((const int*)ei)[e];
        d = ((const int*)ei)[E + e];
    }
    g_src[e] = s;
    g_dst[e] = d;
    atomicAdd(&g_deg[d], 1);
}

__global__ void scan_dinv_kernel(int M, int E) {
    __shared__ int s[1024];
    const int t = threadIdx.x;
    const int CH = (M + 1023) / 1024;
    const int beg = t * CH;
    const int end = min(M, beg + CH);
    int loc = 0;
    for (int i = beg; i < end; i++) loc += g_deg[i];
    s[t] = loc;
    __syncthreads();
    for (int off = 1; off < 1024; off <<= 1) {
        int v = (t >= off) ? s[t - off] : 0;
        __syncthreads();
        s[t] += v;
        __syncthreads();
    }
    int run = s[t] - loc;
    for (int i = beg; i < end; i++) {
        int d = g_deg[i];
        g_rowptr[i] = run;
        g_cursor[i] = run;
        g_dinv[i] = rsqrtf((float)d + 1.0f);
        run += d;
    }
    if (t == 1023) g_rowptr[M] = E;
}

__global__ void fill_kernel(int E) {
    int e = blockIdx.x * blockDim.x + threadIdx.x;
    if (e >= E) return;
    int s = g_src[e];
    int d = g_dst[e];
    int pos = atomicAdd(&g_cursor[d], 1);
    g_csr[pos] = make_int2(s, __float_as_int(g_dinv[s] * g_dinv[d]));
}

// ---------------------------------------------------------------------------
// Split-TF32 tensor-core GEMM: C[:, col0:col0+64] = A[M,128] @ W[:, col0:+64]
// 3-term compensated (Ah*Wh + Ah*Wl + Al*Wh). N=64 columns per block;
// blockIdx.y selects the column half (WLD/LDC = full row strides).
// smem 128*(64+4)*8B = 69.6KB -> 3 CTAs/SM.
// ---------------------------------------------------------------------------
__device__ __forceinline__ uint32_t f2tf32(float x) {
    uint32_t h;
    asm("cvt.rna.tf32.f32 %0, %1;" : "=r"(h) : "f"(x));
    return h;
}
__device__ __forceinline__ void split_tf32(float x, uint32_t& hi, uint32_t& lo) {
    hi = f2tf32(x);
    lo = f2tf32(x - __uint_as_float(hi));
}
__device__ __forceinline__ void mma_tf32(float* c, const uint32_t* a, uint32_t b0, uint32_t b1) {
    asm volatile(
        "mma.sync.aligned.m16n8k8.row.col.f32.tf32.tf32.f32 "
        "{%0,%1,%2,%3}, {%4,%5,%6,%7}, {%8,%9}, {%0,%1,%2,%3};"
        : "+f"(c[0]), "+f"(c[1]), "+f"(c[2]), "+f"(c[3])
        : "r"(a[0]), "r"(a[1]), "r"(a[2]), "r"(a[3]), "r"(b0), "r"(b1));
}

__global__ void __launch_bounds__(256)
gemm_tf32_kernel(const float* __restrict__ A, const float* __restrict__ W,
                 float* __restrict__ C, int M, int wld, int ldc) {
    constexpr int K = 128, N = 64;
    constexpr int LDW = N + 4;            // float2 row stride (conflict-free, see R8)
    constexpr int NT = (N / 2) / 8;       // 4 n-tiles per warp
    extern __shared__ __align__(16) float2 sW[];  // [K][LDW] = {hi, lo}

    const int col0 = blockIdx.y * N;

    const int tid  = threadIdx.x;
    const int warp = tid >> 5;
    const int lane = tid & 31;

    for (int i = tid; i < K * N; i += 256) {
        const int k = i / N, n = i % N;
        float w = W[(long long)k * wld + col0 + n];
        uint32_t h, l;
        split_tf32(w, h, l);
        sW[k * LDW + n] = make_float2(__uint_as_float(h), __uint_as_float(l));
    }
    __syncthreads();

    const int m0 = blockIdx.x * 128 + (warp >> 1) * 32;
    const int n0 = (warp & 1) * (N / 2);
    const int g  = lane >> 2;
    const int tg = lane & 3;

    const float* Arow[4];
    #pragma unroll
    for (int mt = 0; mt < 2; mt++) {
        int r0 = m0 + mt * 16 + g;
        Arow[mt * 2 + 0] = A + (long long)min(r0,     M - 1) * K;
        Arow[mt * 2 + 1] = A + (long long)min(r0 + 8, M - 1) * K;
    }

    float acc[2][NT][4];
    #pragma unroll
    for (int mt = 0; mt < 2; mt++)
        #pragma unroll
        for (int j = 0; j < NT; j++)
            #pragma unroll
            for (int q = 0; q < 4; q++) acc[mt][j][q] = 0.0f;

    const float2* wb = sW + tg * LDW + n0 + g;

    float acur[2][4], anxt[2][4];
    #pragma unroll
    for (int mt = 0; mt < 2; mt++) {
        acur[mt][0] = Arow[mt * 2 + 0][tg];
        acur[mt][1] = Arow[mt * 2 + 1][tg];
        acur[mt][2] = Arow[mt * 2 + 0][tg + 4];
        acur[mt][3] = Arow[mt * 2 + 1][tg + 4];
    }

    #pragma unroll
    for (int k0 = 0; k0 < K; k0 += 8) {
        if (k0 + 8 < K) {
            #pragma unroll
            for (int mt = 0; mt < 2; mt++) {
                anxt[mt][0] = Arow[mt * 2 + 0][k0 + 8 + tg];
                anxt[mt][1] = Arow[mt * 2 + 1][k0 + 8 + tg];
                anxt[mt][2] = Arow[mt * 2 + 0][k0 + 8 + tg + 4];
                anxt[mt][3] = Arow[mt * 2 + 1][k0 + 8 + tg + 4];
            }
        }

        uint32_t ah[2][4], al[2][4];
        #pragma unroll
        for (int mt = 0; mt < 2; mt++)
            #pragma unroll
            for (int q = 0; q < 4; q++)
                split_tf32(acur[mt][q], ah[mt][q], al[mt][q]);

        const float2* wk0 = wb + k0 * LDW;
        #pragma unroll
        for (int j = 0; j < NT; j++) {
            float2 w0 = wk0[j * 8];
            float2 w1 = wk0[4 * LDW + j * 8];
            uint32_t bh0 = __float_as_uint(w0.x), bl0 = __float_as_uint(w0.y);
            uint32_t bh1 = __float_as_uint(w1.x), bl1 = __float_as_uint(w1.y);
            #pragma unroll
            for (int mt = 0; mt < 2; mt++) {
                mma_tf32(acc[mt][j], ah[mt], bh0, bh1);
                mma_tf32(acc[mt][j], ah[mt], bl0, bl1);
                mma_tf32(acc[mt][j], al[mt], bh0, bh1);
            }
        }

        #pragma unroll
        for (int mt = 0; mt < 2; mt++)
            #pragma unroll
            for (int q = 0; q < 4; q++) acur[mt][q] = anxt[mt][q];
    }

    #pragma unroll
    for (int mt = 0; mt < 2; mt++) {
        int r0 = m0 + mt * 16 + g;
        #pragma unroll
        for (int j = 0; j < NT; j++) {
            int col = col0 + n0 + j * 8 + tg * 2;
            if (r0 < M)
                *reinterpret_cast<float2*>(C + (long long)r0 * ldc + col) =
                    make_float2(acc[mt][j][0], acc[mt][j][1]);
            if (r0 + 8 < M)
                *reinterpret_cast<float2*>(C + (long long)(r0 + 8) * ldc + col) =
                    make_float2(acc[mt][j][2], acc[mt][j][3]);
        }
    }
}

// ---------------------------------------------------------------------------
// CSR gather aggregation, one WARP per destination node, unroll x4 (R7).
// ---------------------------------------------------------------------------
template <int F, bool TANH>
__global__ void __launch_bounds__(256)
gather_kernel(const float* __restrict__ xw, const float* __restrict__ bias,
              float* __restrict__ out, int M) {
    const int gw   = (blockIdx.x * blockDim.x + threadIdx.x) >> 5;
    const int lane = threadIdx.x & 31;
    if (gw >= M) return;

    const float di = g_dinv[gw];
    const float cself = di * di;
    const int beg = g_rowptr[gw];
    const int end = g_rowptr[gw + 1];

    if (F == 128) {
        float4 v  = reinterpret_cast<const float4*>(xw + (long long)gw * F)[lane];
        float4 bb = reinterpret_cast<const float4*>(bias)[lane];
        float4 acc = make_float4(fmaf(v.x, cself, bb.x), fmaf(v.y, cself, bb.y),
                                 fmaf(v.z, cself, bb.z), fmaf(v.w, cself, bb.w));
        int j = beg;
        for (; j + 4 <= end; j += 4) {
            int2 c0 = g_csr[j],     c1 = g_csr[j + 1];
            int2 c2 = g_csr[j + 2], c3 = g_csr[j + 3];
            float4 a0 = reinterpret_cast<const float4*>(xw + (long long)c0.x * F)[lane];
            float4 a1 = reinterpret_cast<const float4*>(xw + (long long)c1.x * F)[lane];
            float4 a2 = reinterpret_cast<const float4*>(xw + (long long)c2.x * F)[lane];
            float4 a3 = reinterpret_cast<const float4*>(xw + (long long)c3.x * F)[lane];
            float w0 = __int_as_float(c0.y), w1 = __int_as_float(c1.y);
            float w2 = __int_as_float(c2.y), w3 = __int_as_float(c3.y);
            acc.x = fmaf(a0.x, w0, fmaf(a1.x, w1, fmaf(a2.x, w2, fmaf(a3.x, w3, acc.x))));
            acc.y = fmaf(a0.y, w0, fmaf(a1.y, w1, fmaf(a2.y, w2, fmaf(a3.y, w3, acc.y))));
            acc.z = fmaf(a0.z, w0, fmaf(a1.z, w1, fmaf(a2.z, w2, fmaf(a3.z, w3, acc.z))));
            acc.w = fmaf(a0.w, w0, fmaf(a1.w, w1, fmaf(a2.w, w2, fmaf(a3.w, w3, acc.w))));
        }
        for (; j < end; j++) {
            int2 c0 = g_csr[j];
            float w0 = __int_as_float(c0.y);
            float4 a = reinterpret_cast<const float4*>(xw + (long long)c0.x * F)[lane];
            acc.x = fmaf(a.x, w0, acc.x);
            acc.y = fmaf(a.y, w0, acc.y);
            acc.z = fmaf(a.z, w0, acc.z);
            acc.w = fmaf(a.w, w0, acc.w);
        }
        if (TANH) {
            acc.x = fast_tanhf(acc.x); acc.y = fast_tanhf(acc.y);
            acc.z = fast_tanhf(acc.z); acc.w = fast_tanhf(acc.w);
        }
        reinterpret_cast<float4*>(out + (long long)gw * F)[lane] = acc;
    } else {  // F == 64
        float2 v  = reinterpret_cast<const float2*>(xw + (long long)gw * F)[lane];
        float2 bb = reinterpret_cast<const float2*>(bias)[lane];
        float2 acc = make_float2(fmaf(v.x, cself, bb.x), fmaf(v.y, cself, bb.y));
        int j = beg;
        for (; j + 4 <= end; j += 4) {
            int2 c0 = g_csr[j],     c1 = g_csr[j + 1];
            int2 c2 = g_csr[j + 2], c3 = g_csr[j + 3];
            float2 a0 = reinterpret_cast<const float2*>(xw + (long long)c0.x * F)[lane];
            float2 a1 = reinterpret_cast<const float2*>(xw + (long long)c1.x * F)[lane];
            float2 a2 = reinterpret_cast<const float2*>(xw + (long long)c2.x * F)[lane];
            float2 a3 = reinterpret_cast<const float2*>(xw + (long long)c3.x * F)[lane];
            float w0 = __int_as_float(c0.y), w1 = __int_as_float(c1.y);
            float w2 = __int_as_float(c2.y), w3 = __int_as_float(c3.y);
            acc.x = fmaf(a0.x, w0, fmaf(a1.x, w1, fmaf(a2.x, w2, fmaf(a3.x, w3, acc.x))));
            acc.y = fmaf(a0.y, w0, fmaf(a1.y, w1, fmaf(a2.y, w2, fmaf(a3.y, w3, acc.y))));
        }
        for (; j < end; j++) {
            int2 c0 = g_csr[j];
            float w0 = __int_as_float(c0.y);
            float2 a = reinterpret_cast<const float2*>(xw + (long long)c0.x * F)[lane];
            acc.x = fmaf(a.x, w0, acc.x);
            acc.y = fmaf(a.y, w0, acc.y);
        }
        if (TANH) { acc.x = fast_tanhf(acc.x); acc.y = fast_tanhf(acc.y); }
        reinterpret_cast<float2*>(out + (long long)gw * F)[lane] = acc;
    }
}

// ---------------------------------------------------------------------------
// Fused FC head: out[i] = tanh( tanh(agg2[i,:]) @ W3 + b3 ) @ W4 + b4
// ---------------------------------------------------------------------------
__global__ void __launch_bounds__(128)
fc_fused_kernel(const float* __restrict__ agg2,
                const float* __restrict__ W3, const float* __restrict__ b3,
                const float* __restrict__ W4, const float* __restrict__ b4,
                float* __restrict__ out, int M) {
    __shared__ __align__(16) float W3t[64 * 64];
    __shared__ float sW4[64];
    __shared__ float sb3[64];

    const int tid = threadIdx.x;
    for (int i = tid; i < 64 * 64; i += blockDim.x) {
        int k = i >> 6, j = i & 63;
        W3t[j * 64 + k] = W3[i];
    }
    if (tid < 64) { sW4[tid] = W4[tid]; sb3[tid] = b3[tid]; }
    __syncthreads();

    const int row = blockIdx.x * blockDim.x + tid;
    if (row >= M) return;

    float h[64];
    const float4* ap = reinterpret_cast<const float4*>(agg2 + (long long)row * 64);
    #pragma unroll
    for (int k4 = 0; k4 < 16; k4++) {
        float4 v = ap[k4];
        h[4 * k4 + 0] = fast_tanhf(v.x);
        h[4 * k4 + 1] = fast_tanhf(v.y);
        h[4 * k4 + 2] = fast_tanhf(v.z);
        h[4 * k4 + 3] = fast_tanhf(v.w);
    }

    float o = 0.0f;
    #pragma unroll
    for (int jt = 0; jt < 4; jt++) {
        float t[16];
        #pragma unroll
        for (int j = 0; j < 16; j++) t[j] = sb3[jt * 16 + j];
        #pragma unroll
        for (int k4 = 0; k4 < 16; k4++) {
            #pragma unroll
            for (int j = 0; j < 16; j++) {
                float4 w = *reinterpret_cast<const float4*>(&W3t[(jt * 16 + j) * 64 + 4 * k4]);
                t[j] = fmaf(h[4 * k4 + 0], w.x,
                        fmaf(h[4 * k4 + 1], w.y,
                         fmaf(h[4 * k4 + 2], w.z,
                          fmaf(h[4 * k4 + 3], w.w, t[j]))));
            }
        }
        #pragma unroll
        for (int j = 0; j < 16; j++) o = fmaf(fast_tanhf(t[j]), sW4[jt * 16 + j], o);
    }
    out[row] = o + b4[0];
}

// ---------------------------------------------------------------------------
// Preload + side-stream + smem opt-in (static init; capture-safe use).
// ---------------------------------------------------------------------------
namespace {
cudaStream_t g_s2 = nullptr;
cudaEvent_t  g_ev_fork = nullptr, g_ev_join = nullptr;
bool g_overlap_ok = false;
constexpr int GEMM_SMEM = 128 * (64 + 4) * (int)sizeof(float2);  // 69.6KB

struct ModulePreloader {
    ModulePreloader() {
        cudaFree(0);
        void* p = nullptr;
        cudaGetSymbolAddress(&p, g_big1);
        cudaGetSymbolAddress(&p, g_big2);
        cudaFuncAttributes a;
        cudaFuncGetAttributes(&a, (const void*)convert_count_kernel);
        cudaFuncGetAttributes(&a, (const void*)scan_dinv_kernel);
        cudaFuncGetAttributes(&a, (const void*)fill_kernel);
        cudaFuncGetAttributes(&a, (const void*)gemm_tf32_kernel);
        cudaFuncGetAttributes(&a, (const void*)gather_kernel<128, true>);
        cudaFuncGetAttributes(&a, (const void*)gather_kernel<64, false>);
        cudaFuncGetAttributes(&a, (const void*)fc_fused_kernel);

        cudaFuncSetAttribute((const void*)gemm_tf32_kernel,
                             cudaFuncAttributeMaxDynamicSharedMemorySize, GEMM_SMEM);

        bool ok = (cudaStreamCreateWithFlags(&g_s2, cudaStreamNonBlocking) == cudaSuccess);
        ok = ok && (cudaEventCreateWithFlags(&g_ev_fork, cudaEventDisableTiming) == cudaSuccess);
        ok = ok && (cudaEventCreateWithFlags(&g_ev_join, cudaEventDisableTiming) == cudaSuccess);
        g_overlap_ok = ok;
    }
};
ModulePreloader g_preloader;
}

// ---------------------------------------------------------------------------
// Launch
// ---------------------------------------------------------------------------
extern "C" void kernel_launch(void* const* d_in, const int* in_sizes, int n_in,
                              void* d_out, int out_size) {
    const float* x  = (const float*)d_in[0];
    const void*  ei = d_in[1];
    const float* W1 = (const float*)d_in[2];
    const float* b1 = (const float*)d_in[3];
    const float* W2 = (const float*)d_in[4];
    const float* b2 = (const float*)d_in[5];
    const float* W3 = (const float*)d_in[6];
    const float* b3 = (const float*)d_in[7];
    const float* W4 = (const float*)d_in[8];
    const float* b4 = (const float*)d_in[9];
    float* out = (float*)d_out;

    const int H1  = in_sizes[3];            // 128
    const int M   = in_sizes[0] / H1;       // 50000 (FIN == H1 == 128)
    const int E   = in_sizes[1] / 2;        // 800000
    const int T = 256;

    float* big1 = nullptr; float* big2 = nullptr; int* degp = nullptr;
    cudaGetSymbolAddress((void**)&big1, g_big1);
    cudaGetSymbolAddress((void**)&big2, g_big2);
    cudaGetSymbolAddress((void**)&degp, g_deg);

    float* xw1  = big1;                               // [M,128]
    float* h1   = big2;                               // [M,128]
    float* xw2  = big1;                               // [M,64]
    float* agg2 = big1 + (long long)MAX_NODES * 64;   // [M,64]

    cudaStream_t sp = (g_overlap_ok ? g_s2 : (cudaStream_t)0);

    if (g_overlap_ok) {
        cudaEventRecord(g_ev_fork, 0);
        cudaStreamWaitEvent(sp, g_ev_fork, 0);
    }

    // --- CSR build chain (stream sp), overlapped with gemm1 ---
    cudaMemsetAsync(degp, 0, M * sizeof(int), sp);
    convert_count_kernel<<<(E + T - 1) / T, T, 0, sp>>>(ei, E);
    scan_dinv_kernel<<<1, 1024, 0, sp>>>(M, E);
    fill_kernel<<<(E + T - 1) / T, T, 0, sp>>>(E);

    // --- gemm1 (tensor cores, 2 column halves via grid.y) ---
    {
        dim3 grid((M + 127) / 128, 2);
        gemm_tf32_kernel<<<grid, T, GEMM_SMEM>>>(x, W1, xw1, M, 128, 128);
    }

    if (g_overlap_ok) {
        cudaEventRecord(g_ev_join, sp);
        cudaStreamWaitEvent(0, g_ev_join, 0);
    }

    // --- Layer 1 aggregation: h1 = tanh(gather(xw1) + self + b1) ---
    gather_kernel<128, true><<<(M + 7) / 8, T>>>(xw1, b1, h1, M);

    // --- Layer 2: xw2 = h1@W2 ; agg2 = gather(xw2) + self + b2 ---
    {
        dim3 grid((M + 127) / 128, 1);
        gemm_tf32_kernel<<<grid, T, GEMM_SMEM>>>(h1, W2, xw2, M, 64, 64);
    }
    gather_kernel<64, false><<<(M + 7) / 8, T>>>(xw2, b2, agg2, M);

    // --- FC head ---
    fc_fused_kernel<<<(M + 127) / 128, 128>>>(agg2, W3, b3, W4, b4, out, M);
}

// round 11
// speedup vs baseline: 1.0751x; 1.0751x over previous
#include <cuda_runtime.h>
#include <cuda_bf16.h>
#include <math.h>
#include <stdlib.h>
#include <stdint.h>

// ---------------------------------------------------------------------------
// BrainGCN: 2x GCNConv(+tanh) then 2 FC layers.
// R11: tf32 GEMM rebuilt with coalesced smem-staged A (was per-lane scalar
// LDG in fragment layout -> L1 65%, occ 22%, tensor 33%). A staged per
// 64-wide K chunk, conflict-free LDS fragments. Rest as R9.
// ---------------------------------------------------------------------------

namespace {
struct EnvInit {  // must run before any CUDA call (lazy-load workaround, R4)
    EnvInit() { setenv("CUDA_MODULE_LOADING", "EAGER", 1); }
};
EnvInit g_env_init;
}

#define MAX_NODES 50000
#define MAX_EDGES 800000

__device__ int   g_deg[MAX_NODES];
__device__ float g_dinv[MAX_NODES];
__device__ int   g_src[MAX_EDGES];
__device__ int   g_dst[MAX_EDGES];
__device__ int   g_rowptr[MAX_NODES + 1];
__device__ int   g_cursor[MAX_NODES];
__device__ int2  g_csr[MAX_EDGES];       // {src, __float_as_int(coef)}

// Aliasing: big1 = xw1[M,128], later xw2[M,64] + agg2[M,64]. big2 = h1[M,128].
__device__ float g_big1[MAX_NODES * 128];
__device__ float g_big2[MAX_NODES * 128];

// ---------------------------------------------------------------------------
// Fast tanh: (e^2x - 1)/(e^2x + 1), ~2e-7 abs err.
// ---------------------------------------------------------------------------
__device__ __forceinline__ float fast_tanhf(float x) {
    float xc = fminf(fmaxf(x, -15.0f), 15.0f);
    float t = __expf(2.0f * xc);
    return __fdividef(t - 1.0f, t + 1.0f);
}

// ---------------------------------------------------------------------------
// Fused convert + degree count (per-block dtype detection, R9).
// ---------------------------------------------------------------------------
__global__ void convert_count_kernel(const void* __restrict__ ei, int E) {
    const unsigned int* w = (const unsigned int*)ei;
    int is64 = 1;
    #pragma unroll
    for (int i = 0; i < 16; i++)
        if (w[2 * i + 1] != 0u) is64 = 0;

    int e = blockIdx.x * blockDim.x + threadIdx.x;
    if (e >= E) return;
    int s, d;
    if (is64) {
        s = (int)((const long long*)ei)[e];
        d = (int)((const long long*)ei)[E + e];
    } else {
        s = ((const int*)ei)[e];
        d = ((const int*)ei)[E + e];
    }
    g_src[e] = s;
    g_dst[e] = d;
    atomicAdd(&g_deg[d], 1);
}

__global__ void scan_dinv_kernel(int M, int E) {
    __shared__ int s[1024];
    const int t = threadIdx.x;
    const int CH = (M + 1023) / 1024;
    const int beg = t * CH;
    const int end = min(M, beg + CH);
    int loc = 0;
    for (int i = beg; i < end; i++) loc += g_deg[i];
    s[t] = loc;
    __syncthreads();
    for (int off = 1; off < 1024; off <<= 1) {
        int v = (t >= off) ? s[t - off] : 0;
        __syncthreads();
        s[t] += v;
        __syncthreads();
    }
    int run = s[t] - loc;
    for (int i = beg; i < end; i++) {
        int d = g_deg[i];
        g_rowptr[i] = run;
        g_cursor[i] = run;
        g_dinv[i] = rsqrtf((float)d + 1.0f);
        run += d;
    }
    if (t == 1023) g_rowptr[M] = E;
}

__global__ void fill_kernel(int E) {
    int e = blockIdx.x * blockDim.x + threadIdx.x;
    if (e >= E) return;
    int s = g_src[e];
    int d = g_dst[e];
    int pos = atomicAdd(&g_cursor[d], 1);
    g_csr[pos] = make_int2(s, __float_as_int(g_dinv[s] * g_dinv[d]));
}

// ---------------------------------------------------------------------------
// Split-TF32 tensor-core GEMM v2: C[:,col0:col0+64] = A[M,128] @ W[:,col0:+64]
// 3-term compensated (Ah*Wh + Ah*Wl + Al*Wh).
// A staged in smem per 64-k chunk, coalesced float4 loads, row-major [128][68]
// (fragment LDS bank index (4g+tg)&31 -> conflict-free). W pre-split float2
// [128][68]. smem 69.6+34.8 = 104.4KB -> 2 CTAs/SM.
// ---------------------------------------------------------------------------
__device__ __forceinline__ uint32_t f2tf32(float x) {
    uint32_t h;
    asm("cvt.rna.tf32.f32 %0, %1;" : "=r"(h) : "f"(x));
    return h;
}
__device__ __forceinline__ void split_tf32(float x, uint32_t& hi, uint32_t& lo) {
    hi = f2tf32(x);
    lo = f2tf32(x - __uint_as_float(hi));
}
__device__ __forceinline__ void mma_tf32(float* c, const uint32_t* a, uint32_t b0, uint32_t b1) {
    asm volatile(
        "mma.sync.aligned.m16n8k8.row.col.f32.tf32.tf32.f32 "
        "{%0,%1,%2,%3}, {%4,%5,%6,%7}, {%8,%9}, {%0,%1,%2,%3};"
        : "+f"(c[0]), "+f"(c[1]), "+f"(c[2]), "+f"(c[3])
        : "r"(a[0]), "r"(a[1]), "r"(a[2]), "r"(a[3]), "r"(b0), "r"(b1));
}

namespace {
constexpr int GEMM_W_BYTES = 128 * 68 * (int)sizeof(float2);  // 69632
constexpr int GEMM_A_BYTES = 128 * 68 * (int)sizeof(float);   // 34816
constexpr int GEMM_SMEM    = GEMM_W_BYTES + GEMM_A_BYTES;     // 104448
}

__global__ void __launch_bounds__(256)
gemm_tf32_kernel(const float* __restrict__ A, const float* __restrict__ W,
                 float* __restrict__ C, int M, int wld, int ldc) {
    constexpr int K = 128, N = 64, BK = 64;
    constexpr int LDW = N + 4;   // float2 stride for W rows
    constexpr int LDA = BK + 4;  // float stride for A smem rows (68)
    constexpr int NT = 4;        // 4 n-tiles of 8 per warp (warp tile 32x32)
    extern __shared__ __align__(16) char smem_raw[];
    float2* sW = reinterpret_cast<float2*>(smem_raw);
    float*  sA = reinterpret_cast<float*>(smem_raw + GEMM_W_BYTES);

    const int tid  = threadIdx.x;
    const int warp = tid >> 5;
    const int lane = tid & 31;
    const int col0 = blockIdx.y * N;
    const int bm   = blockIdx.x * 128;

    // stage W (all 128 k rows, pre-split hi/lo)
    for (int i = tid; i < K * N; i += 256) {
        int k = i >> 6, n = i & 63;
        float w = W[(long long)k * wld + col0 + n];
        uint32_t h, l;
        split_tf32(w, h, l);
        sW[k * LDW + n] = make_float2(__uint_as_float(h), __uint_as_float(l));
    }

    const int m0 = (warp >> 1) * 32;   // local 32-row band
    const int n0 = (warp & 1) * 32;    // n half within N=64
    const int g  = lane >> 2;
    const int tg = lane & 3;

    float acc[2][NT][4] = {};

    const float2* wb = sW + tg * LDW + n0 + g;

    #pragma unroll
    for (int ch = 0; ch < 2; ch++) {
        __syncthreads();  // chunk0: orders W staging too; chunk1: waits mma readers
        // stage A chunk: rows 0..127, k in [ch*64, ch*64+64), coalesced float4
        for (int i = tid; i < 128 * 16; i += 256) {
            int row = i >> 4;
            int kq  = (i & 15) << 2;
            int grow = min(bm + row, M - 1);
            float4 v = *reinterpret_cast<const float4*>(A + (long long)grow * K + ch * BK + kq);
            *reinterpret_cast<float4*>(&sA[row * LDA + kq]) = v;
        }
        __syncthreads();

        #pragma unroll
        for (int k0 = 0; k0 < BK; k0 += 8) {
            uint32_t ah[2][4], al[2][4];
            #pragma unroll
            for (int mt = 0; mt < 2; mt++) {
                int r0 = m0 + mt * 16 + g;
                float a0 = sA[r0 * LDA + k0 + tg];
                float a1 = sA[(r0 + 8) * LDA + k0 + tg];
                float a2 = sA[r0 * LDA + k0 + tg + 4];
                float a3 = sA[(r0 + 8) * LDA + k0 + tg + 4];
                split_tf32(a0, ah[mt][0], al[mt][0]);
                split_tf32(a1, ah[mt][1], al[mt][1]);
                split_tf32(a2, ah[mt][2], al[mt][2]);
                split_tf32(a3, ah[mt][3], al[mt][3]);
            }
            const float2* wk0 = wb + (ch * BK + k0) * LDW;
            #pragma unroll
            for (int j = 0; j < NT; j++) {
                float2 w0 = wk0[j * 8];
                float2 w1 = wk0[4 * LDW + j * 8];
                uint32_t bh0 = __float_as_uint(w0.x), bl0 = __float_as_uint(w0.y);
                uint32_t bh1 = __float_as_uint(w1.x), bl1 = __float_as_uint(w1.y);
                #pragma unroll
                for (int mt = 0; mt < 2; mt++) {
                    mma_tf32(acc[mt][j], ah[mt], bh0, bh1);
                    mma_tf32(acc[mt][j], ah[mt], bl0, bl1);
                    mma_tf32(acc[mt][j], al[mt], bh0, bh1);
                }
            }
        }
    }

    #pragma unroll
    for (int mt = 0; mt < 2; mt++) {
        int r0 = bm + m0 + mt * 16 + g;
        #pragma unroll
        for (int j = 0; j < NT; j++) {
            int col = col0 + n0 + j * 8 + tg * 2;
            if (r0 < M)
                *reinterpret_cast<float2*>(C + (long long)r0 * ldc + col) =
                    make_float2(acc[mt][j][0], acc[mt][j][1]);
            if (r0 + 8 < M)
                *reinterpret_cast<float2*>(C + (long long)(r0 + 8) * ldc + col) =
                    make_float2(acc[mt][j][2], acc[mt][j][3]);
        }
    }
}

// ---------------------------------------------------------------------------
// CSR gather aggregation, one WARP per destination node, unroll x4 (R7).
// ---------------------------------------------------------------------------
template <int F, bool TANH>
__global__ void __launch_bounds__(256)
gather_kernel(const float* __restrict__ xw, const float* __restrict__ bias,
              float* __restrict__ out, int M) {
    const int gw   = (blockIdx.x * blockDim.x + threadIdx.x) >> 5;
    const int lane = threadIdx.x & 31;
    if (gw >= M) return;

    const float di = g_dinv[gw];
    const float cself = di * di;
    const int beg = g_rowptr[gw];
    const int end = g_rowptr[gw + 1];

    if (F == 128) {
        float4 v  = reinterpret_cast<const float4*>(xw + (long long)gw * F)[lane];
        float4 bb = reinterpret_cast<const float4*>(bias)[lane];
        float4 acc = make_float4(fmaf(v.x, cself, bb.x), fmaf(v.y, cself, bb.y),
                                 fmaf(v.z, cself, bb.z), fmaf(v.w, cself, bb.w));
        int j = beg;
        for (; j + 4 <= end; j += 4) {
            int2 c0 = g_csr[j],     c1 = g_csr[j + 1];
            int2 c2 = g_csr[j + 2], c3 = g_csr[j + 3];
            float4 a0 = reinterpret_cast<const float4*>(xw + (long long)c0.x * F)[lane];
            float4 a1 = reinterpret_cast<const float4*>(xw + (long long)c1.x * F)[lane];
            float4 a2 = reinterpret_cast<const float4*>(xw + (long long)c2.x * F)[lane];
            float4 a3 = reinterpret_cast<const float4*>(xw + (long long)c3.x * F)[lane];
            float w0 = __int_as_float(c0.y), w1 = __int_as_float(c1.y);
            float w2 = __int_as_float(c2.y), w3 = __int_as_float(c3.y);
            acc.x = fmaf(a0.x, w0, fmaf(a1.x, w1, fmaf(a2.x, w2, fmaf(a3.x, w3, acc.x))));
            acc.y = fmaf(a0.y, w0, fmaf(a1.y, w1, fmaf(a2.y, w2, fmaf(a3.y, w3, acc.y))));
            acc.z = fmaf(a0.z, w0, fmaf(a1.z, w1, fmaf(a2.z, w2, fmaf(a3.z, w3, acc.z))));
            acc.w = fmaf(a0.w, w0, fmaf(a1.w, w1, fmaf(a2.w, w2, fmaf(a3.w, w3, acc.w))));
        }
        for (; j < end; j++) {
            int2 c0 = g_csr[j];
            float w0 = __int_as_float(c0.y);
            float4 a = reinterpret_cast<const float4*>(xw + (long long)c0.x * F)[lane];
            acc.x = fmaf(a.x, w0, acc.x);
            acc.y = fmaf(a.y, w0, acc.y);
            acc.z = fmaf(a.z, w0, acc.z);
            acc.w = fmaf(a.w, w0, acc.w);
        }
        if (TANH) {
            acc.x = fast_tanhf(acc.x); acc.y = fast_tanhf(acc.y);
            acc.z = fast_tanhf(acc.z); acc.w = fast_tanhf(acc.w);
        }
        reinterpret_cast<float4*>(out + (long long)gw * F)[lane] = acc;
    } else {  // F == 64
        float2 v  = reinterpret_cast<const float2*>(xw + (long long)gw * F)[lane];
        float2 bb = reinterpret_cast<const float2*>(bias)[lane];
        float2 acc = make_float2(fmaf(v.x, cself, bb.x), fmaf(v.y, cself, bb.y));
        int j = beg;
        for (; j + 4 <= end; j += 4) {
            int2 c0 = g_csr[j],     c1 = g_csr[j + 1];
            int2 c2 = g_csr[j + 2], c3 = g_csr[j + 3];
            float2 a0 = reinterpret_cast<const float2*>(xw + (long long)c0.x * F)[lane];
            float2 a1 = reinterpret_cast<const float2*>(xw + (long long)c1.x * F)[lane];
            float2 a2 = reinterpret_cast<const float2*>(xw + (long long)c2.x * F)[lane];
            float2 a3 = reinterpret_cast<const float2*>(xw + (long long)c3.x * F)[lane];
            float w0 = __int_as_float(c0.y), w1 = __int_as_float(c1.y);
            float w2 = __int_as_float(c2.y), w3 = __int_as_float(c3.y);
            acc.x = fmaf(a0.x, w0, fmaf(a1.x, w1, fmaf(a2.x, w2, fmaf(a3.x, w3, acc.x))));
            acc.y = fmaf(a0.y, w0, fmaf(a1.y, w1, fmaf(a2.y, w2, fmaf(a3.y, w3, acc.y))));
        }
        for (; j < end; j++) {
            int2 c0 = g_csr[j];
            float w0 = __int_as_float(c0.y);
            float2 a = reinterpret_cast<const float2*>(xw + (long long)c0.x * F)[lane];
            acc.x = fmaf(a.x, w0, acc.x);
            acc.y = fmaf(a.y, w0, acc.y);
        }
        if (TANH) { acc.x = fast_tanhf(acc.x); acc.y = fast_tanhf(acc.y); }
        reinterpret_cast<float2*>(out + (long long)gw * F)[lane] = acc;
    }
}

// ---------------------------------------------------------------------------
// Fused FC head: out[i] = tanh( tanh(agg2[i,:]) @ W3 + b3 ) @ W4 + b4
// ---------------------------------------------------------------------------
__global__ void __launch_bounds__(128)
fc_fused_kernel(const float* __restrict__ agg2,
                const float* __restrict__ W3, const float* __restrict__ b3,
                const float* __restrict__ W4, const float* __restrict__ b4,
                float* __restrict__ out, int M) {
    __shared__ __align__(16) float W3t[64 * 64];
    __shared__ float sW4[64];
    __shared__ float sb3[64];

    const int tid = threadIdx.x;
    for (int i = tid; i < 64 * 64; i += blockDim.x) {
        int k = i >> 6, j = i & 63;
        W3t[j * 64 + k] = W3[i];
    }
    if (tid < 64) { sW4[tid] = W4[tid]; sb3[tid] = b3[tid]; }
    __syncthreads();

    const int row = blockIdx.x * blockDim.x + tid;
    if (row >= M) return;

    float h[64];
    const float4* ap = reinterpret_cast<const float4*>(agg2 + (long long)row * 64);
    #pragma unroll
    for (int k4 = 0; k4 < 16; k4++) {
        float4 v = ap[k4];
        h[4 * k4 + 0] = fast_tanhf(v.x);
        h[4 * k4 + 1] = fast_tanhf(v.y);
        h[4 * k4 + 2] = fast_tanhf(v.z);
        h[4 * k4 + 3] = fast_tanhf(v.w);
    }

    float o = 0.0f;
    #pragma unroll
    for (int jt = 0; jt < 4; jt++) {
        float t[16];
        #pragma unroll
        for (int j = 0; j < 16; j++) t[j] = sb3[jt * 16 + j];
        #pragma unroll
        for (int k4 = 0; k4 < 16; k4++) {
            #pragma unroll
            for (int j = 0; j < 16; j++) {
                float4 w = *reinterpret_cast<const float4*>(&W3t[(jt * 16 + j) * 64 + 4 * k4]);
                t[j] = fmaf(h[4 * k4 + 0], w.x,
                        fmaf(h[4 * k4 + 1], w.y,
                         fmaf(h[4 * k4 + 2], w.z,
                          fmaf(h[4 * k4 + 3], w.w, t[j]))));
            }
        }
        #pragma unroll
        for (int j = 0; j < 16; j++) o = fmaf(fast_tanhf(t[j]), sW4[jt * 16 + j], o);
    }
    out[row] = o + b4[0];
}

// ---------------------------------------------------------------------------
// Preload + side-stream + smem opt-in (static init; capture-safe use).
// ---------------------------------------------------------------------------
namespace {
cudaStream_t g_s2 = nullptr;
cudaEvent_t  g_ev_fork = nullptr, g_ev_join = nullptr;
bool g_overlap_ok = false;

struct ModulePreloader {
    ModulePreloader() {
        cudaFree(0);
        void* p = nullptr;
        cudaGetSymbolAddress(&p, g_big1);
        cudaGetSymbolAddress(&p, g_big2);
        cudaFuncAttributes a;
        cudaFuncGetAttributes(&a, (const void*)convert_count_kernel);
        cudaFuncGetAttributes(&a, (const void*)scan_dinv_kernel);
        cudaFuncGetAttributes(&a, (const void*)fill_kernel);
        cudaFuncGetAttributes(&a, (const void*)gemm_tf32_kernel);
        cudaFuncGetAttributes(&a, (const void*)gather_kernel<128, true>);
        cudaFuncGetAttributes(&a, (const void*)gather_kernel<64, false>);
        cudaFuncGetAttributes(&a, (const void*)fc_fused_kernel);

        cudaFuncSetAttribute((const void*)gemm_tf32_kernel,
                             cudaFuncAttributeMaxDynamicSharedMemorySize, GEMM_SMEM);

        bool ok = (cudaStreamCreateWithFlags(&g_s2, cudaStreamNonBlocking) == cudaSuccess);
        ok = ok && (cudaEventCreateWithFlags(&g_ev_fork, cudaEventDisableTiming) == cudaSuccess);
        ok = ok && (cudaEventCreateWithFlags(&g_ev_join, cudaEventDisableTiming) == cudaSuccess);
        g_overlap_ok = ok;
    }
};
ModulePreloader g_preloader;
}

// ---------------------------------------------------------------------------
// Launch
// ---------------------------------------------------------------------------
extern "C" void kernel_launch(void* const* d_in, const int* in_sizes, int n_in,
                              void* d_out, int out_size) {
    const float* x  = (const float*)d_in[0];
    const void*  ei = d_in[1];
    const float* W1 = (const float*)d_in[2];
    const float* b1 = (const float*)d_in[3];
    const float* W2 = (const float*)d_in[4];
    const float* b2 = (const float*)d_in[5];
    const float* W3 = (const float*)d_in[6];
    const float* b3 = (const float*)d_in[7];
    const float* W4 = (const float*)d_in[8];
    const float* b4 = (const float*)d_in[9];
    float* out = (float*)d_out;

    const int H1  = in_sizes[3];            // 128
    const int M   = in_sizes[0] / H1;       // 50000 (FIN == H1 == 128)
    const int E   = in_sizes[1] / 2;        // 800000
    const int T = 256;

    float* big1 = nullptr; float* big2 = nullptr; int* degp = nullptr;
    cudaGetSymbolAddress((void**)&big1, g_big1);
    cudaGetSymbolAddress((void**)&big2, g_big2);
    cudaGetSymbolAddress((void**)&degp, g_deg);

    float* xw1  = big1;                               // [M,128]
    float* h1   = big2;                               // [M,128]
    float* xw2  = big1;                               // [M,64]
    float* agg2 = big1 + (long long)MAX_NODES * 64;   // [M,64]

    cudaStream_t sp = (g_overlap_ok ? g_s2 : (cudaStream_t)0);

    if (g_overlap_ok) {
        cudaEventRecord(g_ev_fork, 0);
        cudaStreamWaitEvent(sp, g_ev_fork, 0);
    }

    // --- CSR build chain (stream sp), overlapped with gemm1 ---
    cudaMemsetAsync(degp, 0, M * sizeof(int), sp);
    convert_count_kernel<<<(E + T - 1) / T, T, 0, sp>>>(ei, E);
    scan_dinv_kernel<<<1, 1024, 0, sp>>>(M, E);
    fill_kernel<<<(E + T - 1) / T, T, 0, sp>>>(E);

    // --- gemm1 (tensor cores, 2 column halves via grid.y) ---
    {
        dim3 grid((M + 127) / 128, 2);
        gemm_tf32_kernel<<<grid, T, GEMM_SMEM>>>(x, W1, xw1, M, 128, 128);
    }

    if (g_overlap_ok) {
        cudaEventRecord(g_ev_join, sp);
        cudaStreamWaitEvent(0, g_ev_join, 0);
    }

    // --- Layer 1 aggregation: h1 = tanh(gather(xw1) + self + b1) ---
    gather_kernel<128, true><<<(M + 7) / 8, T>>>(xw1, b1, h1, M);

    // --- Layer 2: xw2 = h1@W2 ; agg2 = gather(xw2) + self + b2 ---
    {
        dim3 grid((M + 127) / 128, 1);
        gemm_tf32_kernel<<<grid, T, GEMM_SMEM>>>(h1, W2, xw2, M, 64, 64);
    }
    gather_kernel<64, false><<<(M + 7) / 8, T>>>(xw2, b2, agg2, M);

    // --- FC head ---
    fc_fused_kernel<<<(M + 127) / 128, 128>>>(agg2, W3, b3, W4, b4, out, M);
}